// round 3
// baseline (speedup 1.0000x reference)
#include <cuda_runtime.h>
#include <math.h>

#define N_ROWS 4096
#define HID 512
#define TSTEPS 12
#define KZX 256
#define G3 1536
#define LDW_IH 258

// Scratch (device globals; no allocation allowed)
__device__ float g_zx[N_ROWS * KZX];   // concat(z, x)           4 MB
__device__ float g_h [N_ROWS * HID];   // hidden state           8 MB
__device__ float g_gi[N_ROWS * G3];    // gi_zx precomputed     24 MB
__device__ float g_gh[N_ROWS * G3];    // gh per step           24 MB
__device__ float g_x [N_ROWS * 2];     // current action x_t

// ---------------------------------------------------------------------------
// Build zx = concat(z, x)
// ---------------------------------------------------------------------------
__global__ void zx_kernel(const float* __restrict__ z, const float* __restrict__ x) {
    int i = blockIdx.x * blockDim.x + threadIdx.x;
    if (i >= N_ROWS * 128) return;
    int row = i >> 7;
    int c = i & 127;
    g_zx[row * KZX + c]       = z[i];
    g_zx[row * KZX + 128 + c] = x[i];
}

// ---------------------------------------------------------------------------
// a0 = x_0 @ W_ia.T + b_ia   (initial action)
// ---------------------------------------------------------------------------
__global__ void a0_kernel(const float* __restrict__ x0,
                          const float* __restrict__ W_ia,
                          const float* __restrict__ b_ia) {
    int row = blockIdx.x * blockDim.x + threadIdx.x;
    if (row >= N_ROWS) return;
    float v0 = x0[row * 4 + 0], v1 = x0[row * 4 + 1];
    float v2 = x0[row * 4 + 2], v3 = x0[row * 4 + 3];
#pragma unroll
    for (int c = 0; c < 2; ++c) {
        g_x[row * 2 + c] = b_ia[c] + v0 * W_ia[c * 4 + 0] + v1 * W_ia[c * 4 + 1]
                                   + v2 * W_ia[c * 4 + 2] + v3 * W_ia[c * 4 + 3];
    }
}

// ---------------------------------------------------------------------------
// C[N, M] = A[N, K(lda)] @ W[M, K(ldw)].T + b[M]
// BM=128, BN=64, BK=16, 256 threads, 8x4 per thread.
// N=4096 fixed; M % 64 == 0; K % 16 == 0 (all true here).
// W loads are scalar (ldw=258 breaks float4 alignment).
// ---------------------------------------------------------------------------
__global__ __launch_bounds__(256, 2)
void sgemm_bias(const float* __restrict__ A, int lda,
                const float* __restrict__ W, int ldw,
                const float* __restrict__ b,
                float* __restrict__ C, int ldc, int K) {
    const int BM = 128, BN = 64, BK = 16;
    __shared__ float As[BK][BM];
    __shared__ float Ws[BK][BN];

    int tid = threadIdx.x;
    int tx = tid & 15;        // col group (BN/4 = 16)
    int ty = tid >> 4;        // row group (BM/8 = 16)
    int rowBase = blockIdx.y * BM;
    int colBase = blockIdx.x * BN;

    // A-load mapping: 512 float4 per tile / 256 threads = 2 each
    int arow0 = tid >> 2;          // 0..63 (second half: +64)
    int ak    = (tid & 3) * 4;     // 0,4,8,12
    // W-load mapping: 64 rows x 16 k / 256 threads = 4 scalars each
    int wn = tid >> 2;             // 0..63
    int wk = (tid & 3) * 4;

    float acc[8][4];
#pragma unroll
    for (int i = 0; i < 8; ++i)
#pragma unroll
        for (int j = 0; j < 4; ++j) acc[i][j] = 0.f;

    for (int k0 = 0; k0 < K; k0 += BK) {
#pragma unroll
        for (int half = 0; half < 2; ++half) {
            int r = arow0 + half * 64;
            float4 a4 = *reinterpret_cast<const float4*>(
                &A[(size_t)(rowBase + r) * lda + k0 + ak]);
            As[ak + 0][r] = a4.x;
            As[ak + 1][r] = a4.y;
            As[ak + 2][r] = a4.z;
            As[ak + 3][r] = a4.w;
        }
        {
            const float* wp = &W[(size_t)(colBase + wn) * ldw + k0 + wk];
            Ws[wk + 0][wn] = wp[0];
            Ws[wk + 1][wn] = wp[1];
            Ws[wk + 2][wn] = wp[2];
            Ws[wk + 3][wn] = wp[3];
        }
        __syncthreads();

#pragma unroll
        for (int k = 0; k < BK; ++k) {
            float ra[8], rb[4];
            float4 t0 = *reinterpret_cast<const float4*>(&As[k][ty * 8]);
            float4 t1 = *reinterpret_cast<const float4*>(&As[k][ty * 8 + 4]);
            ra[0] = t0.x; ra[1] = t0.y; ra[2] = t0.z; ra[3] = t0.w;
            ra[4] = t1.x; ra[5] = t1.y; ra[6] = t1.z; ra[7] = t1.w;
            float4 w4 = *reinterpret_cast<const float4*>(&Ws[k][tx * 4]);
            rb[0] = w4.x; rb[1] = w4.y; rb[2] = w4.z; rb[3] = w4.w;
#pragma unroll
            for (int i = 0; i < 8; ++i)
#pragma unroll
                for (int j = 0; j < 4; ++j)
                    acc[i][j] = fmaf(ra[i], rb[j], acc[i][j]);
        }
        __syncthreads();
    }

#pragma unroll
    for (int i = 0; i < 8; ++i) {
        int row = rowBase + ty * 8 + i;
#pragma unroll
        for (int j = 0; j < 4; ++j) {
            int col = colBase + tx * 4 + j;
            C[(size_t)row * ldc + col] = acc[i][j] + b[col];
        }
    }
}

// ---------------------------------------------------------------------------
// Fused gate math + hidden update + output projection for one time step.
// One block per row, 128 threads, 4 hidden units per thread.
//   gi = gi_zx + x_t @ W_ih[:,256:258].T      (rank-2 correction)
//   r = sig(gi_r + gh_r); u = sig(gi_z + gh_z); n = tanh(gi_n + r*gh_n)
//   h' = (1-u)*n + u*h
//   out = h' @ W_out.T + b_out  -> d_out[row][t][:], and becomes next x_t
// ---------------------------------------------------------------------------
__global__ __launch_bounds__(128)
void gate_kernel(const float* __restrict__ W_ih,
                 const float* __restrict__ W_out,
                 const float* __restrict__ b_out,
                 float* __restrict__ out, int t) {
    int row = blockIdx.x;
    int tid = threadIdx.x;
    float xa = g_x[row * 2 + 0];
    float xb = g_x[row * 2 + 1];

    int j0 = tid * 4;
    const float* gi = &g_gi[(size_t)row * G3];
    const float* gh = &g_gh[(size_t)row * G3];

    float gir[4], giz[4], gin[4], ghr[4], ghz[4], ghn[4], hv[4], hn[4];
    *reinterpret_cast<float4*>(gir) = *reinterpret_cast<const float4*>(&gi[j0]);
    *reinterpret_cast<float4*>(giz) = *reinterpret_cast<const float4*>(&gi[512 + j0]);
    *reinterpret_cast<float4*>(gin) = *reinterpret_cast<const float4*>(&gi[1024 + j0]);
    *reinterpret_cast<float4*>(ghr) = *reinterpret_cast<const float4*>(&gh[j0]);
    *reinterpret_cast<float4*>(ghz) = *reinterpret_cast<const float4*>(&gh[512 + j0]);
    *reinterpret_cast<float4*>(ghn) = *reinterpret_cast<const float4*>(&gh[1024 + j0]);
    *reinterpret_cast<float4*>(hv)  = *reinterpret_cast<const float4*>(&g_h[(size_t)row * HID + j0]);

    float o0 = 0.f, o1 = 0.f;
#pragma unroll
    for (int i = 0; i < 4; ++i) {
        int j = j0 + i;
        float gi_r = gir[i] + xa * W_ih[(size_t)j * LDW_IH + 256]
                            + xb * W_ih[(size_t)j * LDW_IH + 257];
        float gi_z = giz[i] + xa * W_ih[(size_t)(512 + j) * LDW_IH + 256]
                            + xb * W_ih[(size_t)(512 + j) * LDW_IH + 257];
        float gi_n = gin[i] + xa * W_ih[(size_t)(1024 + j) * LDW_IH + 256]
                            + xb * W_ih[(size_t)(1024 + j) * LDW_IH + 257];
        float r = 1.f / (1.f + expf(-(gi_r + ghr[i])));
        float u = 1.f / (1.f + expf(-(gi_z + ghz[i])));
        float n = tanhf(gi_n + r * ghn[i]);
        float h_new = (1.f - u) * n + u * hv[i];
        hn[i] = h_new;
        o0 += h_new * W_out[j];
        o1 += h_new * W_out[HID + j];
    }
    *reinterpret_cast<float4*>(&g_h[(size_t)row * HID + j0]) =
        make_float4(hn[0], hn[1], hn[2], hn[3]);

    // block reduction for the 2 outputs
    unsigned m = 0xffffffffu;
#pragma unroll
    for (int off = 16; off; off >>= 1) {
        o0 += __shfl_down_sync(m, o0, off);
        o1 += __shfl_down_sync(m, o1, off);
    }
    __shared__ float s0[4], s1[4];
    int wid = tid >> 5, lane = tid & 31;
    if (lane == 0) { s0[wid] = o0; s1[wid] = o1; }
    __syncthreads();
    if (tid == 0) {
        float r0 = s0[0] + s0[1] + s0[2] + s0[3] + b_out[0];
        float r1 = s1[0] + s1[1] + s1[2] + s1[3] + b_out[1];
        out[row * (TSTEPS * 2) + t * 2 + 0] = r0;
        out[row * (TSTEPS * 2) + t * 2 + 1] = r1;
        g_x[row * 2 + 0] = r0;
        g_x[row * 2 + 1] = r1;
    }
}

// ---------------------------------------------------------------------------
// Host launcher
// ---------------------------------------------------------------------------
static float* sym_addr(const void* sym) {
    void* p = nullptr;
    cudaGetSymbolAddress(&p, sym);
    return reinterpret_cast<float*>(p);
}

extern "C" void kernel_launch(void* const* d_in, const int* in_sizes, int n_in,
                              void* d_out, int out_size) {
    const float* z     = (const float*)d_in[0];
    const float* x     = (const float*)d_in[1];
    const float* x0    = (const float*)d_in[2];
    const float* W_ia  = (const float*)d_in[3];
    const float* b_ia  = (const float*)d_in[4];
    const float* W_h0  = (const float*)d_in[5];
    const float* b_h0  = (const float*)d_in[6];
    const float* W_ih  = (const float*)d_in[7];
    const float* b_ih  = (const float*)d_in[8];
    const float* W_hh  = (const float*)d_in[9];
    const float* b_hh  = (const float*)d_in[10];
    const float* W_out = (const float*)d_in[11];
    const float* b_out = (const float*)d_in[12];
    float* out = (float*)d_out;

    float* p_zx = sym_addr(g_zx);
    float* p_h  = sym_addr(g_h);
    float* p_gi = sym_addr(g_gi);
    float* p_gh = sym_addr(g_gh);

    // Precompute
    zx_kernel<<<(N_ROWS * 128 + 255) / 256, 256>>>(z, x);
    a0_kernel<<<(N_ROWS + 255) / 256, 256>>>(x0, W_ia, b_ia);

    // h0 = zx @ W_h0.T + b_h0        [4096, 512]
    sgemm_bias<<<dim3(HID / 64, N_ROWS / 128), 256>>>(
        p_zx, KZX, W_h0, KZX, b_h0, p_h, HID, KZX);
    // gi_zx = zx @ W_ih[:, :256].T + b_ih   [4096, 1536]
    sgemm_bias<<<dim3(G3 / 64, N_ROWS / 128), 256>>>(
        p_zx, KZX, W_ih, LDW_IH, b_ih, p_gi, G3, KZX);

    // Sequential GRU steps
    for (int t = 0; t < TSTEPS; ++t) {
        // gh = h @ W_hh.T + b_hh      [4096, 1536]
        sgemm_bias<<<dim3(G3 / 64, N_ROWS / 128), 256>>>(
            p_h, HID, W_hh, HID, b_hh, p_gh, G3, HID);
        gate_kernel<<<N_ROWS, 128>>>(W_ih, W_out, b_out, out, t);
    }
}

// round 8
// speedup vs baseline: 3.1675x; 3.1675x over previous
#include <cuda_runtime.h>
#include <cstdint>
#include <math.h>

#define N_ROWS 4096
#define HID 512
#define TSTEPS 12
#define KZX 256
#define G3 1536
#define LDW_IH 258
#define BK 16
#define LDK 20            // padded floats per smem row (conflict-free, 16B-aligned)
#define STG_F (128 * LDK) // floats per stage buffer

// ---------------- device scratch (no allocs allowed) ----------------
__device__ float g_zx [N_ROWS * KZX];   // concat(z,x), tf32-rounded
__device__ float g_h  [N_ROWS * HID];   // hidden state, tf32-rounded
__device__ float g_gi [N_ROWS * G3];    // gi_zx precomputed (fp32)
__device__ float g_gh [N_ROWS * G3];    // gh per step (fp32)
__device__ float g_x  [N_ROWS * 2];     // current action
__device__ float g_wi [G3 * KZX];       // W_ih[:, :256] repacked, tf32
__device__ float g_wh [G3 * HID];       // W_hh, tf32-rounded
__device__ float g_wh0[HID * KZX];      // W_h0, tf32-rounded
__device__ float g_wt [G3 * 2];         // W_ih[:, 256:258] packed (fp32)

// ---------------- helpers ----------------
__device__ __forceinline__ float tf32r(float v) {
    uint32_t u; asm("cvt.rna.tf32.f32 %0, %1;" : "=r"(u) : "f"(v));
    return __uint_as_float(u);
}
__device__ __forceinline__ uint32_t smem_u32(const void* p) {
    uint32_t a;
    asm("{ .reg .u64 t; cvta.to.shared.u64 t, %1; cvt.u32.u64 %0, t; }"
        : "=r"(a) : "l"(p));
    return a;
}

// ---------------- prologue kernels ----------------
__global__ void zx_kernel(const float* __restrict__ z, const float* __restrict__ x) {
    int i = blockIdx.x * blockDim.x + threadIdx.x;
    if (i >= N_ROWS * 128) return;
    int row = i >> 7, c = i & 127;
    g_zx[row * KZX + c]       = tf32r(z[i]);
    g_zx[row * KZX + 128 + c] = tf32r(x[i]);
}

__global__ void a0_kernel(const float* __restrict__ x0,
                          const float* __restrict__ W_ia,
                          const float* __restrict__ b_ia) {
    int row = blockIdx.x * blockDim.x + threadIdx.x;
    if (row >= N_ROWS) return;
    float v0 = x0[row * 4 + 0], v1 = x0[row * 4 + 1];
    float v2 = x0[row * 4 + 2], v3 = x0[row * 4 + 3];
#pragma unroll
    for (int c = 0; c < 2; ++c) {
        g_x[row * 2 + c] = b_ia[c] + v0 * W_ia[c * 4 + 0] + v1 * W_ia[c * 4 + 1]
                                   + v2 * W_ia[c * 4 + 2] + v3 * W_ia[c * 4 + 3];
    }
}

__global__ void pack_wih(const float* __restrict__ W) {
    int i = blockIdx.x * blockDim.x + threadIdx.x;
    if (i >= G3 * KZX) return;
    int r = i >> 8, c = i & 255;
    g_wi[i] = tf32r(W[(size_t)r * LDW_IH + c]);
}
__global__ void pack_whh(const float* __restrict__ W) {
    int i = blockIdx.x * blockDim.x + threadIdx.x;
    if (i >= G3 * HID) return;
    g_wh[i] = tf32r(W[i]);
}
__global__ void pack_wh0(const float* __restrict__ W) {
    int i = blockIdx.x * blockDim.x + threadIdx.x;
    if (i >= HID * KZX) return;
    g_wh0[i] = tf32r(W[i]);
}
__global__ void pack_wt(const float* __restrict__ W) {
    int i = blockIdx.x * blockDim.x + threadIdx.x;
    if (i >= G3 * 2) return;
    int r = i >> 1, c = i & 1;
    g_wt[i] = W[(size_t)r * LDW_IH + 256 + c];
}

// ---------------------------------------------------------------------------
// tf32 mma.sync GEMM:  C[4096, M_out] = A[4096, K] @ W[M_out, K]^T + bias
// CTA 128x128, 8 warps in 2x4 (m x n), each warp 64x32 via m16n8k8 tiles.
// Double-buffered cp.async, BK=16, smem rows padded to LDK=20 floats
// (conflict-free fragment reads, 16B-aligned cp.async destinations).
// ---------------------------------------------------------------------------
__global__ __launch_bounds__(256)
void sgemm_mma(const float* __restrict__ A, int lda,
               const float* __restrict__ W, int ldw,
               const float* __restrict__ bias,
               float* __restrict__ C, int ldc,
               int K, int round_out)
{
    __shared__ float sm[4 * STG_F];   // [A0|A1|B0|B1], 40 KB

    const int tid = threadIdx.x;
    const int wid = tid >> 5;
    const int lane = tid & 31;
    const int gid = lane >> 2;        // 0..7
    const int tig = lane & 3;         // 0..3
    const int warp_m = wid & 1;       // 2 warps along M (64 rows each)
    const int warp_n = wid >> 1;      // 4 warps along N (32 cols each)
    const int rowBase = blockIdx.y * 128;
    const int colBase = blockIdx.x * 128;
    const int NK = K / BK;

    const uint32_t smBase = smem_u32(sm);

    // stage loader: A/B 128 rows x 16 floats each, 512 float4 per operand
    auto load_stage = [&](int ks, int buf) {
        const int k0 = ks * BK;
        const uint32_t aOff = smBase + (uint32_t)(buf * STG_F) * 4u;
        const uint32_t bOff = smBase + (uint32_t)((2 + buf) * STG_F) * 4u;
#pragma unroll
        for (int i = 0; i < 2; ++i) {
            int q = tid + i * 256;       // 0..511
            int r = q >> 2;              // 0..127
            int f = q & 3;               // float4 slot (0..3)
            uint32_t d = (uint32_t)(r * LDK + f * 4) * 4u;
            const float* sa = A + (size_t)(rowBase + r) * lda + k0 + f * 4;
            const float* sw = W + (size_t)(colBase + r) * ldw + k0 + f * 4;
            asm volatile("cp.async.cg.shared.global [%0], [%1], 16;"
                         :: "r"(aOff + d), "l"(sa));
            asm volatile("cp.async.cg.shared.global [%0], [%1], 16;"
                         :: "r"(bOff + d), "l"(sw));
        }
        asm volatile("cp.async.commit_group;" ::: "memory");
    };

    float acc[4][4][4];
#pragma unroll
    for (int mt = 0; mt < 4; ++mt)
#pragma unroll
        for (int nt = 0; nt < 4; ++nt)
#pragma unroll
            for (int c = 0; c < 4; ++c) acc[mt][nt][c] = 0.f;

    load_stage(0, 0);

    for (int ks = 0; ks < NK; ++ks) {
        if (ks + 1 < NK) {
            load_stage(ks + 1, (ks + 1) & 1);
            asm volatile("cp.async.wait_group 1;" ::: "memory");
        } else {
            asm volatile("cp.async.wait_group 0;" ::: "memory");
        }
        __syncthreads();

        const float* As = &sm[(ks & 1) * STG_F];
        const float* Bs = &sm[(2 + (ks & 1)) * STG_F];

#pragma unroll
        for (int kk = 0; kk < BK; kk += 8) {
            float a[4][4], b[4][2];
#pragma unroll
            for (int mt = 0; mt < 4; ++mt) {
                int ar = warp_m * 64 + mt * 16 + gid;
                a[mt][0] = As[ar * LDK + kk + tig];
                a[mt][1] = As[(ar + 8) * LDK + kk + tig];
                a[mt][2] = As[ar * LDK + kk + 4 + tig];
                a[mt][3] = As[(ar + 8) * LDK + kk + 4 + tig];
            }
#pragma unroll
            for (int nt = 0; nt < 4; ++nt) {
                int br = warp_n * 32 + nt * 8 + gid;
                b[nt][0] = Bs[br * LDK + kk + tig];
                b[nt][1] = Bs[br * LDK + kk + 4 + tig];
            }
#pragma unroll
            for (int mt = 0; mt < 4; ++mt)
#pragma unroll
                for (int nt = 0; nt < 4; ++nt) {
                    asm volatile(
                        "mma.sync.aligned.m16n8k8.row.col.f32.tf32.tf32.f32 "
                        "{%0,%1,%2,%3}, {%4,%5,%6,%7}, {%8,%9}, {%0,%1,%2,%3};"
                        : "+f"(acc[mt][nt][0]), "+f"(acc[mt][nt][1]),
                          "+f"(acc[mt][nt][2]), "+f"(acc[mt][nt][3])
                        : "r"(__float_as_uint(a[mt][0])), "r"(__float_as_uint(a[mt][1])),
                          "r"(__float_as_uint(a[mt][2])), "r"(__float_as_uint(a[mt][3])),
                          "r"(__float_as_uint(b[nt][0])), "r"(__float_as_uint(b[nt][1])));
                }
        }
        __syncthreads();
    }

    // epilogue: bias add + (optional tf32 rounding) + float2 stores
#pragma unroll
    for (int mt = 0; mt < 4; ++mt) {
        int row = rowBase + warp_m * 64 + mt * 16 + gid;
#pragma unroll
        for (int nt = 0; nt < 4; ++nt) {
            int col = colBase + warp_n * 32 + nt * 8 + tig * 2;
            float b0 = bias[col], b1 = bias[col + 1];
            float2 v0 = make_float2(acc[mt][nt][0] + b0, acc[mt][nt][1] + b1);
            float2 v1 = make_float2(acc[mt][nt][2] + b0, acc[mt][nt][3] + b1);
            if (round_out) {
                v0.x = tf32r(v0.x); v0.y = tf32r(v0.y);
                v1.x = tf32r(v1.x); v1.y = tf32r(v1.y);
            }
            *reinterpret_cast<float2*>(C + (size_t)row * ldc + col) = v0;
            *reinterpret_cast<float2*>(C + (size_t)(row + 8) * ldc + col) = v1;
        }
    }
}

// ---------------------------------------------------------------------------
// Fused gate math + hidden update + output projection (one block per row).
// ---------------------------------------------------------------------------
__device__ __forceinline__ float fast_sigmoid(float x) {
    return 1.f / (1.f + __expf(-x));
}
__device__ __forceinline__ float fast_tanh(float x) {
    float t = __expf(-2.f * fabsf(x));
    float m = (1.f - t) / (1.f + t);
    return copysignf(m, x);
}

__global__ __launch_bounds__(128)
void gate_kernel(const float* __restrict__ W_out,
                 const float* __restrict__ b_out,
                 float* __restrict__ out, int t) {
    int row = blockIdx.x;
    int tid = threadIdx.x;
    float xa = g_x[row * 2 + 0];
    float xb = g_x[row * 2 + 1];

    int j0 = tid * 4;
    const float* gi = &g_gi[(size_t)row * G3];
    const float* gh = &g_gh[(size_t)row * G3];

    float gir[4], giz[4], gin[4], ghr[4], ghz[4], ghn[4], hv[4];
    *reinterpret_cast<float4*>(gir) = *reinterpret_cast<const float4*>(&gi[j0]);
    *reinterpret_cast<float4*>(giz) = *reinterpret_cast<const float4*>(&gi[512 + j0]);
    *reinterpret_cast<float4*>(gin) = *reinterpret_cast<const float4*>(&gi[1024 + j0]);
    *reinterpret_cast<float4*>(ghr) = *reinterpret_cast<const float4*>(&gh[j0]);
    *reinterpret_cast<float4*>(ghz) = *reinterpret_cast<const float4*>(&gh[512 + j0]);
    *reinterpret_cast<float4*>(ghn) = *reinterpret_cast<const float4*>(&gh[1024 + j0]);
    *reinterpret_cast<float4*>(hv)  = *reinterpret_cast<const float4*>(&g_h[(size_t)row * HID + j0]);

    // packed rank-2 tail weights (coalesced float4 pairs)
    float wr[8], wz[8], wn[8];
    *reinterpret_cast<float4*>(&wr[0]) = *reinterpret_cast<const float4*>(&g_wt[(size_t)j0 * 2]);
    *reinterpret_cast<float4*>(&wr[4]) = *reinterpret_cast<const float4*>(&g_wt[(size_t)j0 * 2 + 4]);
    *reinterpret_cast<float4*>(&wz[0]) = *reinterpret_cast<const float4*>(&g_wt[(size_t)(512 + j0) * 2]);
    *reinterpret_cast<float4*>(&wz[4]) = *reinterpret_cast<const float4*>(&g_wt[(size_t)(512 + j0) * 2 + 4]);
    *reinterpret_cast<float4*>(&wn[0]) = *reinterpret_cast<const float4*>(&g_wt[(size_t)(1024 + j0) * 2]);
    *reinterpret_cast<float4*>(&wn[4]) = *reinterpret_cast<const float4*>(&g_wt[(size_t)(1024 + j0) * 2 + 4]);

    float o0 = 0.f, o1 = 0.f;
    float hn[4];
#pragma unroll
    for (int i = 0; i < 4; ++i) {
        int j = j0 + i;
        float gi_r = gir[i] + xa * wr[i * 2] + xb * wr[i * 2 + 1];
        float gi_z = giz[i] + xa * wz[i * 2] + xb * wz[i * 2 + 1];
        float gi_n = gin[i] + xa * wn[i * 2] + xb * wn[i * 2 + 1];
        float r = fast_sigmoid(gi_r + ghr[i]);
        float u = fast_sigmoid(gi_z + ghz[i]);
        float n = fast_tanh(gi_n + r * ghn[i]);
        float h_new = (1.f - u) * n + u * hv[i];
        hn[i] = h_new;
        o0 += h_new * W_out[j];
        o1 += h_new * W_out[HID + j];
    }
    // store tf32-rounded (next-step MMA operand)
    *reinterpret_cast<float4*>(&g_h[(size_t)row * HID + j0]) =
        make_float4(tf32r(hn[0]), tf32r(hn[1]), tf32r(hn[2]), tf32r(hn[3]));

    unsigned m = 0xffffffffu;
#pragma unroll
    for (int off = 16; off; off >>= 1) {
        o0 += __shfl_down_sync(m, o0, off);
        o1 += __shfl_down_sync(m, o1, off);
    }
    __shared__ float s0[4], s1[4];
    int wi = tid >> 5, lane = tid & 31;
    if (lane == 0) { s0[wi] = o0; s1[wi] = o1; }
    __syncthreads();
    if (tid == 0) {
        float r0 = s0[0] + s0[1] + s0[2] + s0[3] + b_out[0];
        float r1 = s1[0] + s1[1] + s1[2] + s1[3] + b_out[1];
        out[row * (TSTEPS * 2) + t * 2 + 0] = r0;
        out[row * (TSTEPS * 2) + t * 2 + 1] = r1;
        g_x[row * 2 + 0] = r0;
        g_x[row * 2 + 1] = r1;
    }
}

// ---------------------------------------------------------------------------
// Host launcher
// ---------------------------------------------------------------------------
static float* sym_addr(const void* sym) {
    void* p = nullptr;
    cudaGetSymbolAddress(&p, sym);
    return reinterpret_cast<float*>(p);
}

extern "C" void kernel_launch(void* const* d_in, const int* in_sizes, int n_in,
                              void* d_out, int out_size) {
    const float* z     = (const float*)d_in[0];
    const float* x     = (const float*)d_in[1];
    const float* x0    = (const float*)d_in[2];
    const float* W_ia  = (const float*)d_in[3];
    const float* b_ia  = (const float*)d_in[4];
    const float* W_h0  = (const float*)d_in[5];
    const float* b_h0  = (const float*)d_in[6];
    const float* W_ih  = (const float*)d_in[7];
    const float* b_ih  = (const float*)d_in[8];
    const float* W_hh  = (const float*)d_in[9];
    const float* b_hh  = (const float*)d_in[10];
    const float* W_out = (const float*)d_in[11];
    const float* b_out = (const float*)d_in[12];
    float* out = (float*)d_out;

    float* p_zx  = sym_addr(g_zx);
    float* p_h   = sym_addr(g_h);
    float* p_gi  = sym_addr(g_gi);
    float* p_gh  = sym_addr(g_gh);
    float* p_wi  = sym_addr(g_wi);
    float* p_wh  = sym_addr(g_wh);
    float* p_wh0 = sym_addr(g_wh0);

    // prologue
    zx_kernel<<<(N_ROWS * 128 + 255) / 256, 256>>>(z, x);
    a0_kernel<<<(N_ROWS + 255) / 256, 256>>>(x0, W_ia, b_ia);
    pack_wih<<<(G3 * KZX + 255) / 256, 256>>>(W_ih);
    pack_whh<<<(G3 * HID + 255) / 256, 256>>>(W_hh);
    pack_wh0<<<(HID * KZX + 255) / 256, 256>>>(W_h0);
    pack_wt<<<(G3 * 2 + 255) / 256, 256>>>(W_ih);

    // h0 = zx @ W_h0.T + b_h0   [4096, 512], K=256 (tf32-rounded: MMA operand)
    sgemm_mma<<<dim3(HID / 128, N_ROWS / 128), 256>>>(
        p_zx, KZX, p_wh0, KZX, b_h0, p_h, HID, KZX, 1);
    // gi = zx @ W_ih[:,:256].T + b_ih   [4096, 1536], K=256
    sgemm_mma<<<dim3(G3 / 128, N_ROWS / 128), 256>>>(
        p_zx, KZX, p_wi, KZX, b_ih, p_gi, G3, KZX, 0);

    // recurrent steps
    for (int t = 0; t < TSTEPS; ++t) {
        sgemm_mma<<<dim3(G3 / 128, N_ROWS / 128), 256>>>(
            p_h, HID, p_wh, HID, b_hh, p_gh, G3, HID, 0);
        gate_kernel<<<N_ROWS, 128>>>(W_out, b_out, out, t);
    }
}

// round 9
// speedup vs baseline: 3.3038x; 1.0430x over previous
#include <cuda_runtime.h>
#include <cstdint>
#include <math.h>

#define N_ROWS 4096
#define HID 512
#define TSTEPS 12
#define KZX 256
#define G3 1536
#define LDW_IH 258
#define BK 16
#define LDK 20            // padded floats per smem row (conflict-free, 16B-aligned)
#define STG_F (128 * LDK) // floats per operand per stage

// ---------------- device scratch (no allocs allowed) ----------------
__device__ float g_zx [N_ROWS * KZX];   // concat(z,x), tf32-rounded
__device__ float g_h  [N_ROWS * HID];   // hidden state, tf32-rounded
__device__ float g_gi [N_ROWS * G3];    // gi_zx precomputed (fp32)
__device__ float g_gh [N_ROWS * G3];    // gh per step (fp32)
__device__ float g_x  [N_ROWS * 2];     // current action
__device__ float g_wi [G3 * KZX];       // W_ih[:, :256] repacked, tf32
__device__ float g_wh [G3 * HID];       // W_hh, tf32-rounded
__device__ float g_wh0[HID * KZX];      // W_h0, tf32-rounded
__device__ float g_wt [G3 * 2];         // W_ih[:, 256:258] packed (fp32)

// ---------------- helpers ----------------
__device__ __forceinline__ float tf32r(float v) {
    uint32_t u; asm("cvt.rna.tf32.f32 %0, %1;" : "=r"(u) : "f"(v));
    return __uint_as_float(u);
}
__device__ __forceinline__ float rcp_fast(float v) {
    float r; asm("rcp.approx.f32 %0, %1;" : "=f"(r) : "f"(v));
    return r;
}
__device__ __forceinline__ uint32_t smem_u32(const void* p) {
    uint32_t a;
    asm("{ .reg .u64 t; cvta.to.shared.u64 t, %1; cvt.u32.u64 %0, t; }"
        : "=r"(a) : "l"(p));
    return a;
}

// ---------------- prologue kernels ----------------
__global__ void zx_kernel(const float* __restrict__ z, const float* __restrict__ x) {
    int i = blockIdx.x * blockDim.x + threadIdx.x;
    if (i >= N_ROWS * 128) return;
    int row = i >> 7, c = i & 127;
    g_zx[row * KZX + c]       = tf32r(z[i]);
    g_zx[row * KZX + 128 + c] = tf32r(x[i]);
}

__global__ void a0_kernel(const float* __restrict__ x0,
                          const float* __restrict__ W_ia,
                          const float* __restrict__ b_ia) {
    int row = blockIdx.x * blockDim.x + threadIdx.x;
    if (row >= N_ROWS) return;
    float v0 = x0[row * 4 + 0], v1 = x0[row * 4 + 1];
    float v2 = x0[row * 4 + 2], v3 = x0[row * 4 + 3];
#pragma unroll
    for (int c = 0; c < 2; ++c) {
        g_x[row * 2 + c] = b_ia[c] + v0 * W_ia[c * 4 + 0] + v1 * W_ia[c * 4 + 1]
                                   + v2 * W_ia[c * 4 + 2] + v3 * W_ia[c * 4 + 3];
    }
}

// One merged pack kernel (keeps launch #6 = first recurrent GEMM for ncu -s 5)
#define PK_WI  (G3 * KZX)                 // 393216
#define PK_WH  (PK_WI + G3 * HID)         // + 786432
#define PK_WH0 (PK_WH + HID * KZX)        // + 131072
#define PK_WT  (PK_WH0 + G3 * 2)          // + 3072
__global__ void pack_all(const float* __restrict__ W_ih,
                         const float* __restrict__ W_hh,
                         const float* __restrict__ W_h0) {
    int i = blockIdx.x * blockDim.x + threadIdx.x;
    if (i < PK_WI) {
        int r = i >> 8, c = i & 255;
        g_wi[i] = tf32r(W_ih[(size_t)r * LDW_IH + c]);
    } else if (i < PK_WH) {
        int j = i - PK_WI;
        g_wh[j] = tf32r(W_hh[j]);
    } else if (i < PK_WH0) {
        int j = i - PK_WH;
        g_wh0[j] = tf32r(W_h0[j]);
    } else if (i < PK_WT) {
        int j = i - PK_WH0;
        int r = j >> 1, c = j & 1;
        g_wt[j] = W_ih[(size_t)r * LDW_IH + 256 + c];
    }
}

// ---------------------------------------------------------------------------
// tf32 mma.sync GEMM:  C[4096, M_out] = A[4096, K] @ W[M_out, K]^T + bias
// CTA 128x128, 4 warps in 2x2, warp tile 64x64 via m16n8k8 (mt=4, nt=8).
// LDS:MMA ratio 1.0 (balanced against the 128B/cyc smem crossbar).
// Double-buffered cp.async, BK=16, LDK=20 padding (conflict-free).
// 2 CTAs/SM (regs ~200, smem 40KB/CTA).
// ---------------------------------------------------------------------------
__global__ __launch_bounds__(128, 2)
void sgemm_mma(const float* __restrict__ A, int lda,
               const float* __restrict__ W, int ldw,
               const float* __restrict__ bias,
               float* __restrict__ C, int ldc,
               int K, int round_out)
{
    __shared__ float sm[4 * STG_F];   // [A0|A1|B0|B1], 40 KB

    const int tid = threadIdx.x;
    const int wid = tid >> 5;
    const int lane = tid & 31;
    const int gid = lane >> 2;        // 0..7
    const int tig = lane & 3;         // 0..3
    const int warp_m = wid & 1;       // 2 warps along M (64 rows each)
    const int warp_n = wid >> 1;      // 2 warps along N (64 cols each)
    const int rowBase = blockIdx.y * 128;
    const int colBase = blockIdx.x * 128;
    const int NK = K / BK;

    const uint32_t smBase = smem_u32(sm);

    // stage loader: A/B 128 rows x 16 floats each = 512 float4 per operand,
    // 128 threads -> 4 float4 each per operand
    auto load_stage = [&](int ks, int buf) {
        const int k0 = ks * BK;
        const uint32_t aOff = smBase + (uint32_t)(buf * STG_F) * 4u;
        const uint32_t bOff = smBase + (uint32_t)((2 + buf) * STG_F) * 4u;
#pragma unroll
        for (int i = 0; i < 4; ++i) {
            int q = tid + i * 128;       // 0..511
            int r = q >> 2;              // 0..127
            int f = q & 3;               // float4 slot (0..3)
            uint32_t d = (uint32_t)(r * LDK + f * 4) * 4u;
            const float* sa = A + (size_t)(rowBase + r) * lda + k0 + f * 4;
            const float* sw = W + (size_t)(colBase + r) * ldw + k0 + f * 4;
            asm volatile("cp.async.cg.shared.global [%0], [%1], 16;"
                         :: "r"(aOff + d), "l"(sa));
            asm volatile("cp.async.cg.shared.global [%0], [%1], 16;"
                         :: "r"(bOff + d), "l"(sw));
        }
        asm volatile("cp.async.commit_group;" ::: "memory");
    };

    float acc[4][8][4];
#pragma unroll
    for (int mt = 0; mt < 4; ++mt)
#pragma unroll
        for (int nt = 0; nt < 8; ++nt)
#pragma unroll
            for (int c = 0; c < 4; ++c) acc[mt][nt][c] = 0.f;

    load_stage(0, 0);

    for (int ks = 0; ks < NK; ++ks) {
        if (ks + 1 < NK) {
            load_stage(ks + 1, (ks + 1) & 1);
            asm volatile("cp.async.wait_group 1;" ::: "memory");
        } else {
            asm volatile("cp.async.wait_group 0;" ::: "memory");
        }
        __syncthreads();

        const float* As = &sm[(ks & 1) * STG_F];
        const float* Bs = &sm[(2 + (ks & 1)) * STG_F];

#pragma unroll
        for (int kk = 0; kk < BK; kk += 8) {
            float a[4][4], b[8][2];
#pragma unroll
            for (int mt = 0; mt < 4; ++mt) {
                int ar = warp_m * 64 + mt * 16 + gid;
                a[mt][0] = As[ar * LDK + kk + tig];
                a[mt][1] = As[(ar + 8) * LDK + kk + tig];
                a[mt][2] = As[ar * LDK + kk + 4 + tig];
                a[mt][3] = As[(ar + 8) * LDK + kk + 4 + tig];
            }
#pragma unroll
            for (int nt = 0; nt < 8; ++nt) {
                int br = warp_n * 64 + nt * 8 + gid;
                b[nt][0] = Bs[br * LDK + kk + tig];
                b[nt][1] = Bs[br * LDK + kk + 4 + tig];
            }
#pragma unroll
            for (int mt = 0; mt < 4; ++mt)
#pragma unroll
                for (int nt = 0; nt < 8; ++nt) {
                    asm volatile(
                        "mma.sync.aligned.m16n8k8.row.col.f32.tf32.tf32.f32 "
                        "{%0,%1,%2,%3}, {%4,%5,%6,%7}, {%8,%9}, {%0,%1,%2,%3};"
                        : "+f"(acc[mt][nt][0]), "+f"(acc[mt][nt][1]),
                          "+f"(acc[mt][nt][2]), "+f"(acc[mt][nt][3])
                        : "r"(__float_as_uint(a[mt][0])), "r"(__float_as_uint(a[mt][1])),
                          "r"(__float_as_uint(a[mt][2])), "r"(__float_as_uint(a[mt][3])),
                          "r"(__float_as_uint(b[nt][0])), "r"(__float_as_uint(b[nt][1])));
                }
        }
        __syncthreads();
    }

    // epilogue: bias add + (optional tf32 rounding) + float2 stores
#pragma unroll
    for (int mt = 0; mt < 4; ++mt) {
        int row = rowBase + warp_m * 64 + mt * 16 + gid;
#pragma unroll
        for (int nt = 0; nt < 8; ++nt) {
            int col = colBase + warp_n * 64 + nt * 8 + tig * 2;
            float b0 = bias[col], b1 = bias[col + 1];
            float2 v0 = make_float2(acc[mt][nt][0] + b0, acc[mt][nt][1] + b1);
            float2 v1 = make_float2(acc[mt][nt][2] + b0, acc[mt][nt][3] + b1);
            if (round_out) {
                v0.x = tf32r(v0.x); v0.y = tf32r(v0.y);
                v1.x = tf32r(v1.x); v1.y = tf32r(v1.y);
            }
            *reinterpret_cast<float2*>(C + (size_t)row * ldc + col) = v0;
            *reinterpret_cast<float2*>(C + (size_t)(row + 8) * ldc + col) = v1;
        }
    }
}

// ---------------------------------------------------------------------------
// Fused gate math + hidden update + output projection (one block per row).
// All transcendentals via MUFU (ex2.approx through __expf, rcp.approx) —
// no div.rn slow paths regardless of harness fast-math flags.
// ---------------------------------------------------------------------------
__device__ __forceinline__ float fast_sigmoid(float x) {
    return rcp_fast(1.f + __expf(-x));
}
__device__ __forceinline__ float fast_tanh(float x) {
    float t = __expf(-2.f * fabsf(x));
    float m = (1.f - t) * rcp_fast(1.f + t);
    return copysignf(m, x);
}

__global__ __launch_bounds__(128)
void gate_kernel(const float* __restrict__ W_out,
                 const float* __restrict__ b_out,
                 float* __restrict__ out, int t) {
    int row = blockIdx.x;
    int tid = threadIdx.x;
    float xa = g_x[row * 2 + 0];
    float xb = g_x[row * 2 + 1];

    int j0 = tid * 4;
    const float* gi = &g_gi[(size_t)row * G3];
    const float* gh = &g_gh[(size_t)row * G3];

    float gir[4], giz[4], gin[4], ghr[4], ghz[4], ghn[4], hv[4];
    *reinterpret_cast<float4*>(gir) = *reinterpret_cast<const float4*>(&gi[j0]);
    *reinterpret_cast<float4*>(giz) = *reinterpret_cast<const float4*>(&gi[512 + j0]);
    *reinterpret_cast<float4*>(gin) = *reinterpret_cast<const float4*>(&gi[1024 + j0]);
    *reinterpret_cast<float4*>(ghr) = *reinterpret_cast<const float4*>(&gh[j0]);
    *reinterpret_cast<float4*>(ghz) = *reinterpret_cast<const float4*>(&gh[512 + j0]);
    *reinterpret_cast<float4*>(ghn) = *reinterpret_cast<const float4*>(&gh[1024 + j0]);
    *reinterpret_cast<float4*>(hv)  = *reinterpret_cast<const float4*>(&g_h[(size_t)row * HID + j0]);

    // packed rank-2 tail weights (coalesced float4 pairs)
    float wr[8], wz[8], wn[8];
    *reinterpret_cast<float4*>(&wr[0]) = *reinterpret_cast<const float4*>(&g_wt[(size_t)j0 * 2]);
    *reinterpret_cast<float4*>(&wr[4]) = *reinterpret_cast<const float4*>(&g_wt[(size_t)j0 * 2 + 4]);
    *reinterpret_cast<float4*>(&wz[0]) = *reinterpret_cast<const float4*>(&g_wt[(size_t)(512 + j0) * 2]);
    *reinterpret_cast<float4*>(&wz[4]) = *reinterpret_cast<const float4*>(&g_wt[(size_t)(512 + j0) * 2 + 4]);
    *reinterpret_cast<float4*>(&wn[0]) = *reinterpret_cast<const float4*>(&g_wt[(size_t)(1024 + j0) * 2]);
    *reinterpret_cast<float4*>(&wn[4]) = *reinterpret_cast<const float4*>(&g_wt[(size_t)(1024 + j0) * 2 + 4]);

    float o0 = 0.f, o1 = 0.f;
    float hn[4];
#pragma unroll
    for (int i = 0; i < 4; ++i) {
        int j = j0 + i;
        float gi_r = gir[i] + xa * wr[i * 2] + xb * wr[i * 2 + 1];
        float gi_z = giz[i] + xa * wz[i * 2] + xb * wz[i * 2 + 1];
        float gi_n = gin[i] + xa * wn[i * 2] + xb * wn[i * 2 + 1];
        float r = fast_sigmoid(gi_r + ghr[i]);
        float u = fast_sigmoid(gi_z + ghz[i]);
        float n = fast_tanh(gi_n + r * ghn[i]);
        float h_new = (1.f - u) * n + u * hv[i];
        hn[i] = h_new;
        o0 += h_new * W_out[j];
        o1 += h_new * W_out[HID + j];
    }
    // store tf32-rounded (next-step MMA operand)
    *reinterpret_cast<float4*>(&g_h[(size_t)row * HID + j0]) =
        make_float4(tf32r(hn[0]), tf32r(hn[1]), tf32r(hn[2]), tf32r(hn[3]));

    unsigned m = 0xffffffffu;
#pragma unroll
    for (int off = 16; off; off >>= 1) {
        o0 += __shfl_down_sync(m, o0, off);
        o1 += __shfl_down_sync(m, o1, off);
    }
    __shared__ float s0[4], s1[4];
    int wi = tid >> 5, lane = tid & 31;
    if (lane == 0) { s0[wi] = o0; s1[wi] = o1; }
    __syncthreads();
    if (tid == 0) {
        float r0 = s0[0] + s0[1] + s0[2] + s0[3] + b_out[0];
        float r1 = s1[0] + s1[1] + s1[2] + s1[3] + b_out[1];
        out[row * (TSTEPS * 2) + t * 2 + 0] = r0;
        out[row * (TSTEPS * 2) + t * 2 + 1] = r1;
        g_x[row * 2 + 0] = r0;
        g_x[row * 2 + 1] = r1;
    }
}

// ---------------------------------------------------------------------------
// Host launcher
// ---------------------------------------------------------------------------
static float* sym_addr(const void* sym) {
    void* p = nullptr;
    cudaGetSymbolAddress(&p, sym);
    return reinterpret_cast<float*>(p);
}

extern "C" void kernel_launch(void* const* d_in, const int* in_sizes, int n_in,
                              void* d_out, int out_size) {
    const float* z     = (const float*)d_in[0];
    const float* x     = (const float*)d_in[1];
    const float* x0    = (const float*)d_in[2];
    const float* W_ia  = (const float*)d_in[3];
    const float* b_ia  = (const float*)d_in[4];
    const float* W_h0  = (const float*)d_in[5];
    const float* b_h0  = (const float*)d_in[6];
    const float* W_ih  = (const float*)d_in[7];
    const float* b_ih  = (const float*)d_in[8];
    const float* W_hh  = (const float*)d_in[9];
    const float* b_hh  = (const float*)d_in[10];
    const float* W_out = (const float*)d_in[11];
    const float* b_out = (const float*)d_in[12];
    float* out = (float*)d_out;

    float* p_zx  = sym_addr(g_zx);
    float* p_h   = sym_addr(g_h);
    float* p_gi  = sym_addr(g_gi);
    float* p_gh  = sym_addr(g_gh);
    float* p_wi  = sym_addr(g_wi);
    float* p_wh  = sym_addr(g_wh);
    float* p_wh0 = sym_addr(g_wh0);

    // prologue (3 launches so the recurrent GEMM is launch #6 for ncu -s 5)
    zx_kernel<<<(N_ROWS * 128 + 255) / 256, 256>>>(z, x);
    a0_kernel<<<(N_ROWS + 255) / 256, 256>>>(x0, W_ia, b_ia);
    pack_all<<<(PK_WT + 255) / 256, 256>>>(W_ih, W_hh, W_h0);

    // h0 = zx @ W_h0.T + b_h0   [4096, 512], K=256 (tf32-rounded: MMA operand)
    sgemm_mma<<<dim3(HID / 128, N_ROWS / 128), 128>>>(
        p_zx, KZX, p_wh0, KZX, b_h0, p_h, HID, KZX, 1);
    // gi = zx @ W_ih[:,:256].T + b_ih   [4096, 1536], K=256
    sgemm_mma<<<dim3(G3 / 128, N_ROWS / 128), 128>>>(
        p_zx, KZX, p_wi, KZX, b_ih, p_gi, G3, KZX, 0);

    // recurrent steps
    for (int t = 0; t < TSTEPS; ++t) {
        sgemm_mma<<<dim3(G3 / 128, N_ROWS / 128), 128>>>(
            p_h, HID, p_wh, HID, b_hh, p_gh, G3, HID, 0);
        gate_kernel<<<N_ROWS, 128>>>(W_out, b_out, out, t);
    }
}

// round 10
// speedup vs baseline: 4.3088x; 1.3042x over previous
#include <cuda_runtime.h>
#include <cstdint>
#include <math.h>

#define N_ROWS 4096
#define HID 512
#define TSTEPS 12
#define KZX 256
#define G3 1536
#define LDW_IH 258
#define BKC 32                 // K per stage
#define STAGE_BYTES 32768      // A 16KB + B 16KB per stage
#define NSTAGE 3
#define DSMEM (NSTAGE * STAGE_BYTES)

// ---------------- device scratch (no allocs allowed) ----------------
__device__ float g_zx [N_ROWS * KZX];   // concat(z,x), tf32-rounded
__device__ float g_h  [N_ROWS * HID];   // hidden state, tf32-rounded
__device__ float g_gi [N_ROWS * G3];    // gi_zx precomputed (fp32)
__device__ float g_gh [N_ROWS * G3];    // gh per step (fp32)
__device__ float g_x  [N_ROWS * 2];     // current action
__device__ float g_wi [G3 * KZX];       // W_ih[:, :256] repacked, tf32
__device__ float g_wh [G3 * HID];       // W_hh, tf32-rounded
__device__ float g_wh0[HID * KZX];      // W_h0, tf32-rounded
__device__ float g_wt [G3 * 2];         // W_ih[:, 256:258] packed (fp32)

// ---------------- helpers ----------------
__device__ __forceinline__ float tf32r(float v) {
    uint32_t u; asm("cvt.rna.tf32.f32 %0, %1;" : "=r"(u) : "f"(v));
    return __uint_as_float(u);
}
__device__ __forceinline__ float rcp_fast(float v) {
    float r; asm("rcp.approx.f32 %0, %1;" : "=f"(r) : "f"(v));
    return r;
}
__device__ __forceinline__ uint32_t smem_u32(const void* p) {
    uint32_t a;
    asm("{ .reg .u64 t; cvta.to.shared.u64 t, %1; cvt.u32.u64 %0, t; }"
        : "=r"(a) : "l"(p));
    return a;
}
__device__ __forceinline__ float lds_f32(uint32_t addr) {
    float v; asm volatile("ld.shared.f32 %0, [%1];" : "=f"(v) : "r"(addr));
    return v;
}
__device__ __forceinline__ void cp16(uint32_t dst, const void* src) {
    asm volatile("cp.async.cg.shared.global [%0], [%1], 16;" :: "r"(dst), "l"(src));
}

// ---------------- prologue kernels ----------------
__global__ void zx_kernel(const float* __restrict__ z, const float* __restrict__ x) {
    int i = blockIdx.x * blockDim.x + threadIdx.x;
    if (i >= N_ROWS * 128) return;
    int row = i >> 7, c = i & 127;
    g_zx[row * KZX + c]       = tf32r(z[i]);
    g_zx[row * KZX + 128 + c] = tf32r(x[i]);
}

__global__ void a0_kernel(const float* __restrict__ x0,
                          const float* __restrict__ W_ia,
                          const float* __restrict__ b_ia) {
    int row = blockIdx.x * blockDim.x + threadIdx.x;
    if (row >= N_ROWS) return;
    float v0 = x0[row * 4 + 0], v1 = x0[row * 4 + 1];
    float v2 = x0[row * 4 + 2], v3 = x0[row * 4 + 3];
#pragma unroll
    for (int c = 0; c < 2; ++c) {
        g_x[row * 2 + c] = b_ia[c] + v0 * W_ia[c * 4 + 0] + v1 * W_ia[c * 4 + 1]
                                   + v2 * W_ia[c * 4 + 2] + v3 * W_ia[c * 4 + 3];
    }
}

// One merged pack kernel
#define PK_WI  (G3 * KZX)
#define PK_WH  (PK_WI + G3 * HID)
#define PK_WH0 (PK_WH + HID * KZX)
#define PK_WT  (PK_WH0 + G3 * 2)
__global__ void pack_all(const float* __restrict__ W_ih,
                         const float* __restrict__ W_hh,
                         const float* __restrict__ W_h0) {
    int i = blockIdx.x * blockDim.x + threadIdx.x;
    if (i < PK_WI) {
        int r = i >> 8, c = i & 255;
        g_wi[i] = tf32r(W_ih[(size_t)r * LDW_IH + c]);
    } else if (i < PK_WH) {
        int j = i - PK_WI;
        g_wh[j] = tf32r(W_hh[j]);
    } else if (i < PK_WH0) {
        int j = i - PK_WH;
        g_wh0[j] = tf32r(W_h0[j]);
    } else if (i < PK_WT) {
        int j = i - PK_WH0;
        int r = j >> 1, c = j & 1;
        g_wt[j] = W_ih[(size_t)r * LDW_IH + 256 + c];
    }
}

// ---------------------------------------------------------------------------
// tf32 mma.sync GEMM:  C[4096, M_out] = A[4096, K] @ W[M_out, K]^T + bias
// CTA 128x128, 4 warps (2x2), warp tile 64x64 via m16n8k8.
// BK=32 stages, 3-stage cp.async pipeline, XOR-swizzled smem (no padding),
// register fragment double-buffering across the 4 kk-blocks per stage.
// 2 CTAs/SM (96KB dynamic smem each).
// Smem layout per stage/operand: row r (0..127) x chunk c (0..7, 16B):
//   byte = r*128 + ((c ^ (r&7)) << 4)    -> conflict-free loads & stores.
// ---------------------------------------------------------------------------
__global__ __launch_bounds__(128, 2)
void sgemm_mma(const float* __restrict__ A, int lda,
               const float* __restrict__ W, int ldw,
               const float* __restrict__ bias,
               float* __restrict__ C, int ldc,
               int K, int round_out)
{
    extern __shared__ char smraw[];
    const int tid = threadIdx.x;
    const int wid = tid >> 5;
    const int lane = tid & 31;
    const int gid = lane >> 2;        // 0..7
    const int tig = lane & 3;         // 0..3
    const int warp_m = wid & 1;
    const int warp_n = wid >> 1;
    const int rowBase = blockIdx.y * 128;
    const int colBase = blockIdx.x * 128;
    const int NK = K / BKC;

    const uint32_t smBase = smem_u32(smraw);

    // stage loader: per operand 128 rows x 8 chunks(16B); 8 chunks/thread each
    auto load_stage = [&](int ks, int slot) {
        const int k0 = ks * BKC;
        const uint32_t aOff = smBase + (uint32_t)slot * STAGE_BYTES;
        const uint32_t bOff = aOff + 16384u;
#pragma unroll
        for (int i = 0; i < 8; ++i) {
            int q = tid + i * 128;        // 0..1023
            int r = q >> 3;               // 0..127
            int c = q & 7;                // chunk
            uint32_t d = (uint32_t)(r * 128 + ((c ^ (r & 7)) << 4));
            cp16(aOff + d, A + (size_t)(rowBase + r) * lda + k0 + c * 4);
            cp16(bOff + d, W + (size_t)(colBase + r) * ldw + k0 + c * 4);
        }
        asm volatile("cp.async.commit_group;" ::: "memory");
    };

    float acc[4][8][4];
#pragma unroll
    for (int mt = 0; mt < 4; ++mt)
#pragma unroll
        for (int nt = 0; nt < 8; ++nt)
#pragma unroll
            for (int c = 0; c < 4; ++c) acc[mt][nt][c] = 0.f;

    float fa[2][4][4], fb[2][8][2];

    // fragment loader for kk-block (kk = 0,8,16,24) from stage base
    auto load_frags = [&](uint32_t aOff, uint32_t bOff, int kk, int buf) {
        const int c0 = kk >> 2;           // lower-half chunk
#pragma unroll
        for (int mt = 0; mt < 4; ++mt) {
            int ar = warp_m * 64 + mt * 16 + gid;   // ar&7 == gid
            uint32_t rb = aOff + (uint32_t)(ar * 128) + (uint32_t)(tig * 4);
            uint32_t rb8 = rb + 8 * 128;
            uint32_t ch0 = (uint32_t)(((c0)     ^ gid) << 4);
            uint32_t ch1 = (uint32_t)(((c0 + 1) ^ gid) << 4);
            fa[buf][mt][0] = lds_f32(rb  + ch0);
            fa[buf][mt][1] = lds_f32(rb8 + ch0);
            fa[buf][mt][2] = lds_f32(rb  + ch1);
            fa[buf][mt][3] = lds_f32(rb8 + ch1);
        }
#pragma unroll
        for (int nt = 0; nt < 8; ++nt) {
            int br = warp_n * 64 + nt * 8 + gid;    // br&7 == gid
            uint32_t rb = bOff + (uint32_t)(br * 128) + (uint32_t)(tig * 4);
            uint32_t ch0 = (uint32_t)(((c0)     ^ gid) << 4);
            uint32_t ch1 = (uint32_t)(((c0 + 1) ^ gid) << 4);
            fb[buf][nt][0] = lds_f32(rb + ch0);
            fb[buf][nt][1] = lds_f32(rb + ch1);
        }
    };

    auto mma_all = [&](int buf) {
#pragma unroll
        for (int mt = 0; mt < 4; ++mt)
#pragma unroll
            for (int nt = 0; nt < 8; ++nt) {
                asm volatile(
                    "mma.sync.aligned.m16n8k8.row.col.f32.tf32.tf32.f32 "
                    "{%0,%1,%2,%3}, {%4,%5,%6,%7}, {%8,%9}, {%0,%1,%2,%3};"
                    : "+f"(acc[mt][nt][0]), "+f"(acc[mt][nt][1]),
                      "+f"(acc[mt][nt][2]), "+f"(acc[mt][nt][3])
                    : "r"(__float_as_uint(fa[buf][mt][0])), "r"(__float_as_uint(fa[buf][mt][1])),
                      "r"(__float_as_uint(fa[buf][mt][2])), "r"(__float_as_uint(fa[buf][mt][3])),
                      "r"(__float_as_uint(fb[buf][nt][0])), "r"(__float_as_uint(fb[buf][nt][1])));
            }
    };

    // 3-stage pipeline: stages 0,1 in flight before loop
    load_stage(0, 0);
    load_stage(1, 1);

    for (int ks = 0; ks < NK; ++ks) {
        if (ks + 1 < NK) {
            asm volatile("cp.async.wait_group 1;" ::: "memory");
        } else {
            asm volatile("cp.async.wait_group 0;" ::: "memory");
        }
        __syncthreads();

        const int slot = ks % NSTAGE;
        const uint32_t aOff = smBase + (uint32_t)slot * STAGE_BYTES;
        const uint32_t bOff = aOff + 16384u;

        load_frags(aOff, bOff, 0, 0);
#pragma unroll
        for (int kk = 0; kk < 4; ++kk) {
            if (kk < 3) load_frags(aOff, bOff, (kk + 1) * 8, (kk + 1) & 1);
            mma_all(kk & 1);
        }
        __syncthreads();

        if (ks + 2 < NK) load_stage(ks + 2, (ks + 2) % NSTAGE);
    }

    // epilogue: bias add + (optional tf32 rounding) + float2 stores
#pragma unroll
    for (int mt = 0; mt < 4; ++mt) {
        int row = rowBase + warp_m * 64 + mt * 16 + gid;
#pragma unroll
        for (int nt = 0; nt < 8; ++nt) {
            int col = colBase + warp_n * 64 + nt * 8 + tig * 2;
            float b0 = bias[col], b1 = bias[col + 1];
            float2 v0 = make_float2(acc[mt][nt][0] + b0, acc[mt][nt][1] + b1);
            float2 v1 = make_float2(acc[mt][nt][2] + b0, acc[mt][nt][3] + b1);
            if (round_out) {
                v0.x = tf32r(v0.x); v0.y = tf32r(v0.y);
                v1.x = tf32r(v1.x); v1.y = tf32r(v1.y);
            }
            *reinterpret_cast<float2*>(C + (size_t)row * ldc + col) = v0;
            *reinterpret_cast<float2*>(C + (size_t)(row + 8) * ldc + col) = v1;
        }
    }
}

// ---------------------------------------------------------------------------
// Fused gate math + hidden update + output projection.
// 2 rows per 256-thread block; 128 threads per row, 4 hidden units/thread.
// MUFU-only transcendentals.
// ---------------------------------------------------------------------------
__device__ __forceinline__ float fast_sigmoid(float x) {
    return rcp_fast(1.f + __expf(-x));
}
__device__ __forceinline__ float fast_tanh(float x) {
    float t = __expf(-2.f * fabsf(x));
    float m = (1.f - t) * rcp_fast(1.f + t);
    return copysignf(m, x);
}

__global__ __launch_bounds__(256)
void gate_kernel(const float* __restrict__ W_out,
                 const float* __restrict__ b_out,
                 float* __restrict__ out, int t) {
    int tid = threadIdx.x;
    int row = blockIdx.x * 2 + (tid >> 7);
    int wt = tid & 127;               // thread within row
    float xa = g_x[row * 2 + 0];
    float xb = g_x[row * 2 + 1];

    int j0 = wt * 4;
    const float* gi = &g_gi[(size_t)row * G3];
    const float* gh = &g_gh[(size_t)row * G3];

    float gir[4], giz[4], gin[4], ghr[4], ghz[4], ghn[4], hv[4];
    *reinterpret_cast<float4*>(gir) = *reinterpret_cast<const float4*>(&gi[j0]);
    *reinterpret_cast<float4*>(giz) = *reinterpret_cast<const float4*>(&gi[512 + j0]);
    *reinterpret_cast<float4*>(gin) = *reinterpret_cast<const float4*>(&gi[1024 + j0]);
    *reinterpret_cast<float4*>(ghr) = *reinterpret_cast<const float4*>(&gh[j0]);
    *reinterpret_cast<float4*>(ghz) = *reinterpret_cast<const float4*>(&gh[512 + j0]);
    *reinterpret_cast<float4*>(ghn) = *reinterpret_cast<const float4*>(&gh[1024 + j0]);
    *reinterpret_cast<float4*>(hv)  = *reinterpret_cast<const float4*>(&g_h[(size_t)row * HID + j0]);

    float wr[8], wz[8], wn[8];
    *reinterpret_cast<float4*>(&wr[0]) = *reinterpret_cast<const float4*>(&g_wt[(size_t)j0 * 2]);
    *reinterpret_cast<float4*>(&wr[4]) = *reinterpret_cast<const float4*>(&g_wt[(size_t)j0 * 2 + 4]);
    *reinterpret_cast<float4*>(&wz[0]) = *reinterpret_cast<const float4*>(&g_wt[(size_t)(512 + j0) * 2]);
    *reinterpret_cast<float4*>(&wz[4]) = *reinterpret_cast<const float4*>(&g_wt[(size_t)(512 + j0) * 2 + 4]);
    *reinterpret_cast<float4*>(&wn[0]) = *reinterpret_cast<const float4*>(&g_wt[(size_t)(1024 + j0) * 2]);
    *reinterpret_cast<float4*>(&wn[4]) = *reinterpret_cast<const float4*>(&g_wt[(size_t)(1024 + j0) * 2 + 4]);

    float o0 = 0.f, o1 = 0.f;
    float hn[4];
#pragma unroll
    for (int i = 0; i < 4; ++i) {
        int j = j0 + i;
        float gi_r = gir[i] + xa * wr[i * 2] + xb * wr[i * 2 + 1];
        float gi_z = giz[i] + xa * wz[i * 2] + xb * wz[i * 2 + 1];
        float gi_n = gin[i] + xa * wn[i * 2] + xb * wn[i * 2 + 1];
        float r = fast_sigmoid(gi_r + ghr[i]);
        float u = fast_sigmoid(gi_z + ghz[i]);
        float n = fast_tanh(gi_n + r * ghn[i]);
        float h_new = (1.f - u) * n + u * hv[i];
        hn[i] = h_new;
        o0 += h_new * W_out[j];
        o1 += h_new * W_out[HID + j];
    }
    *reinterpret_cast<float4*>(&g_h[(size_t)row * HID + j0]) =
        make_float4(tf32r(hn[0]), tf32r(hn[1]), tf32r(hn[2]), tf32r(hn[3]));

    unsigned m = 0xffffffffu;
#pragma unroll
    for (int off = 16; off; off >>= 1) {
        o0 += __shfl_down_sync(m, o0, off);
        o1 += __shfl_down_sync(m, o1, off);
    }
    __shared__ float s0[8], s1[8];
    int wi = tid >> 5, lane = tid & 31;   // wi 0..7; warps 0-3 row A, 4-7 row B
    if (lane == 0) { s0[wi] = o0; s1[wi] = o1; }
    __syncthreads();
    if (wt == 0) {
        int base = (tid >> 7) * 4;
        float r0 = s0[base] + s0[base + 1] + s0[base + 2] + s0[base + 3] + b_out[0];
        float r1 = s1[base] + s1[base + 1] + s1[base + 2] + s1[base + 3] + b_out[1];
        out[row * (TSTEPS * 2) + t * 2 + 0] = r0;
        out[row * (TSTEPS * 2) + t * 2 + 1] = r1;
        g_x[row * 2 + 0] = r0;
        g_x[row * 2 + 1] = r1;
    }
}

// ---------------------------------------------------------------------------
// Host launcher
// ---------------------------------------------------------------------------
static float* sym_addr(const void* sym) {
    void* p = nullptr;
    cudaGetSymbolAddress(&p, sym);
    return reinterpret_cast<float*>(p);
}

extern "C" void kernel_launch(void* const* d_in, const int* in_sizes, int n_in,
                              void* d_out, int out_size) {
    const float* z     = (const float*)d_in[0];
    const float* x     = (const float*)d_in[1];
    const float* x0    = (const float*)d_in[2];
    const float* W_ia  = (const float*)d_in[3];
    const float* b_ia  = (const float*)d_in[4];
    const float* W_h0  = (const float*)d_in[5];
    const float* b_h0  = (const float*)d_in[6];
    const float* W_ih  = (const float*)d_in[7];
    const float* b_ih  = (const float*)d_in[8];
    const float* W_hh  = (const float*)d_in[9];
    const float* b_hh  = (const float*)d_in[10];
    const float* W_out = (const float*)d_in[11];
    const float* b_out = (const float*)d_in[12];
    float* out = (float*)d_out;

    float* p_zx  = sym_addr(g_zx);
    float* p_h   = sym_addr(g_h);
    float* p_gi  = sym_addr(g_gi);
    float* p_gh  = sym_addr(g_gh);
    float* p_wi  = sym_addr(g_wi);
    float* p_wh  = sym_addr(g_wh);
    float* p_wh0 = sym_addr(g_wh0);

    cudaFuncSetAttribute(sgemm_mma, cudaFuncAttributeMaxDynamicSharedMemorySize, DSMEM);

    // prologue
    zx_kernel<<<(N_ROWS * 128 + 255) / 256, 256>>>(z, x);
    a0_kernel<<<(N_ROWS + 255) / 256, 256>>>(x0, W_ia, b_ia);
    pack_all<<<(PK_WT + 255) / 256, 256>>>(W_ih, W_hh, W_h0);

    // h0 = zx @ W_h0.T + b_h0   [4096, 512], K=256 (tf32-rounded: MMA operand)
    sgemm_mma<<<dim3(HID / 128, N_ROWS / 128), 128, DSMEM>>>(
        p_zx, KZX, p_wh0, KZX, b_h0, p_h, HID, KZX, 1);
    // gi = zx @ W_ih[:,:256].T + b_ih   [4096, 1536], K=256
    sgemm_mma<<<dim3(G3 / 128, N_ROWS / 128), 128, DSMEM>>>(
        p_zx, KZX, p_wi, KZX, b_ih, p_gi, G3, KZX, 0);

    // recurrent steps
    for (int t = 0; t < TSTEPS; ++t) {
        sgemm_mma<<<dim3(G3 / 128, N_ROWS / 128), 128, DSMEM>>>(
            p_h, HID, p_wh, HID, b_hh, p_gh, G3, HID, 0);
        gate_kernel<<<N_ROWS / 2, 256>>>(W_out, b_out, out, t);
    }
}

// round 11
// speedup vs baseline: 6.5604x; 1.5225x over previous
#include <cuda_runtime.h>
#include <cuda_fp16.h>
#include <cstdint>
#include <math.h>

#define N_ROWS 4096
#define HID 512
#define TSTEPS 12
#define KZX 256
#define G3 1536
#define LDW_IH 258
#define BKC 64                 // K (halves) per stage
#define STAGE_BYTES 32768      // A 16KB + B 16KB per stage
#define NSTAGE 3
#define DSMEM (NSTAGE * STAGE_BYTES)

// ---------------- device scratch (no allocs allowed) ----------------
__device__ __half g_zx [N_ROWS * KZX];  // concat(z,x), fp16
__device__ __half g_h  [N_ROWS * HID];  // hidden state, fp16
__device__ float  g_gi [N_ROWS * G3];   // gi_zx precomputed (fp32)
__device__ float  g_gh [N_ROWS * G3];   // gh per step (fp32)
__device__ float  g_x  [N_ROWS * 2];    // current action
__device__ __half g_wi [G3 * KZX];      // W_ih[:, :256] repacked, fp16
__device__ __half g_wh [G3 * HID];      // W_hh, fp16
__device__ __half g_wh0[HID * KZX];     // W_h0, fp16
__device__ float  g_wt [G3 * 2];        // W_ih[:, 256:258] packed (fp32)

// ---------------- helpers ----------------
__device__ __forceinline__ float rcp_fast(float v) {
    float r; asm("rcp.approx.f32 %0, %1;" : "=f"(r) : "f"(v));
    return r;
}
__device__ __forceinline__ uint32_t smem_u32(const void* p) {
    uint32_t a;
    asm("{ .reg .u64 t; cvta.to.shared.u64 t, %1; cvt.u32.u64 %0, t; }"
        : "=r"(a) : "l"(p));
    return a;
}
__device__ __forceinline__ uint32_t lds_u32(uint32_t addr) {
    uint32_t v; asm volatile("ld.shared.b32 %0, [%1];" : "=r"(v) : "r"(addr));
    return v;
}
__device__ __forceinline__ void cp16(uint32_t dst, const void* src) {
    asm volatile("cp.async.cg.shared.global [%0], [%1], 16;" :: "r"(dst), "l"(src));
}

// ---------------- prologue kernels ----------------
__global__ void zx_kernel(const float* __restrict__ z, const float* __restrict__ x) {
    int i = blockIdx.x * blockDim.x + threadIdx.x;
    if (i >= N_ROWS * 128) return;
    int row = i >> 7, c = i & 127;
    g_zx[row * KZX + c]       = __float2half_rn(z[i]);
    g_zx[row * KZX + 128 + c] = __float2half_rn(x[i]);
}

__global__ void a0_kernel(const float* __restrict__ x0,
                          const float* __restrict__ W_ia,
                          const float* __restrict__ b_ia) {
    int row = blockIdx.x * blockDim.x + threadIdx.x;
    if (row >= N_ROWS) return;
    float v0 = x0[row * 4 + 0], v1 = x0[row * 4 + 1];
    float v2 = x0[row * 4 + 2], v3 = x0[row * 4 + 3];
#pragma unroll
    for (int c = 0; c < 2; ++c) {
        g_x[row * 2 + c] = b_ia[c] + v0 * W_ia[c * 4 + 0] + v1 * W_ia[c * 4 + 1]
                                   + v2 * W_ia[c * 4 + 2] + v3 * W_ia[c * 4 + 3];
    }
}

// One merged pack kernel
#define PK_WI  (G3 * KZX)
#define PK_WH  (PK_WI + G3 * HID)
#define PK_WH0 (PK_WH + HID * KZX)
#define PK_WT  (PK_WH0 + G3 * 2)
__global__ void pack_all(const float* __restrict__ W_ih,
                         const float* __restrict__ W_hh,
                         const float* __restrict__ W_h0) {
    int i = blockIdx.x * blockDim.x + threadIdx.x;
    if (i < PK_WI) {
        int r = i >> 8, c = i & 255;
        g_wi[i] = __float2half_rn(W_ih[(size_t)r * LDW_IH + c]);
    } else if (i < PK_WH) {
        int j = i - PK_WI;
        g_wh[j] = __float2half_rn(W_hh[j]);
    } else if (i < PK_WH0) {
        int j = i - PK_WH;
        g_wh0[j] = __float2half_rn(W_h0[j]);
    } else if (i < PK_WT) {
        int j = i - PK_WH0;
        int r = j >> 1, c = j & 1;
        g_wt[j] = W_ih[(size_t)r * LDW_IH + 256 + c];
    }
}

// ---------------------------------------------------------------------------
// fp16 mma.sync GEMM:  C[4096, M_out] = A[4096, K] @ W[M_out, K]^T + bias
// fp16 operands (same 11-bit significand as tf32), fp32 accumulate.
// CTA 128x128, 4 warps (2x2), warp tile 64x64 via m16n8k16.
// BK=64 halves per stage, 3-stage cp.async pipeline, XOR-swizzled smem.
// Smem: row r (0..127) x chunk c (0..7, 16B = 8 halves):
//   byte = r*128 + ((c ^ (r&7)) << 4)
// out_half: write C as fp16 (h0 path); else fp32 (gi/gh).
// ---------------------------------------------------------------------------
__global__ __launch_bounds__(128, 2)
void sgemm_mma(const __half* __restrict__ A, int lda,
               const __half* __restrict__ W, int ldw,
               const float* __restrict__ bias,
               void* __restrict__ Cv, int ldc,
               int K, int out_half)
{
    extern __shared__ char smraw[];
    const int tid = threadIdx.x;
    const int wid = tid >> 5;
    const int lane = tid & 31;
    const int gid = lane >> 2;        // 0..7
    const int tig = lane & 3;         // 0..3
    const int warp_m = wid & 1;
    const int warp_n = wid >> 1;
    const int rowBase = blockIdx.y * 128;
    const int colBase = blockIdx.x * 128;
    const int NK = K / BKC;

    const uint32_t smBase = smem_u32(smraw);

    // stage loader: per operand 128 rows x 8 chunks (16B = 8 halves)
    auto load_stage = [&](int ks, int slot) {
        const int k0 = ks * BKC;
        const uint32_t aOff = smBase + (uint32_t)slot * STAGE_BYTES;
        const uint32_t bOff = aOff + 16384u;
#pragma unroll
        for (int i = 0; i < 8; ++i) {
            int q = tid + i * 128;        // 0..1023
            int r = q >> 3;               // 0..127
            int c = q & 7;                // chunk
            uint32_t d = (uint32_t)(r * 128 + ((c ^ (r & 7)) << 4));
            cp16(aOff + d, A + (size_t)(rowBase + r) * lda + k0 + c * 8);
            cp16(bOff + d, W + (size_t)(colBase + r) * ldw + k0 + c * 8);
        }
        asm volatile("cp.async.commit_group;" ::: "memory");
    };

    float acc[4][8][4];
#pragma unroll
    for (int mt = 0; mt < 4; ++mt)
#pragma unroll
        for (int nt = 0; nt < 8; ++nt)
#pragma unroll
            for (int c = 0; c < 4; ++c) acc[mt][nt][c] = 0.f;

    uint32_t fa[2][4][4], fb[2][8][2];

    // fragment loader for k16-block kk (0..3): chunks 2kk, 2kk+1
    auto load_frags = [&](uint32_t aOff, uint32_t bOff, int kk, int buf) {
        const uint32_t c0 = (uint32_t)(((2 * kk)     ^ gid) << 4);
        const uint32_t c1 = (uint32_t)(((2 * kk + 1) ^ gid) << 4);
#pragma unroll
        for (int mt = 0; mt < 4; ++mt) {
            int ar = warp_m * 64 + mt * 16 + gid;   // ar&7 == gid
            uint32_t rb = aOff + (uint32_t)(ar * 128) + (uint32_t)(tig * 4);
            fa[buf][mt][0] = lds_u32(rb + c0);             // (row, k 2tig..+1)
            fa[buf][mt][1] = lds_u32(rb + 8 * 128 + c0);   // (row+8, same)
            fa[buf][mt][2] = lds_u32(rb + c1);             // (row, k+8)
            fa[buf][mt][3] = lds_u32(rb + 8 * 128 + c1);   // (row+8, k+8)
        }
#pragma unroll
        for (int nt = 0; nt < 8; ++nt) {
            int br = warp_n * 64 + nt * 8 + gid;    // br&7 == gid
            uint32_t rb = bOff + (uint32_t)(br * 128) + (uint32_t)(tig * 4);
            fb[buf][nt][0] = lds_u32(rb + c0);
            fb[buf][nt][1] = lds_u32(rb + c1);
        }
    };

    auto mma_all = [&](int buf) {
#pragma unroll
        for (int mt = 0; mt < 4; ++mt)
#pragma unroll
            for (int nt = 0; nt < 8; ++nt) {
                asm volatile(
                    "mma.sync.aligned.m16n8k16.row.col.f32.f16.f16.f32 "
                    "{%0,%1,%2,%3}, {%4,%5,%6,%7}, {%8,%9}, {%0,%1,%2,%3};"
                    : "+f"(acc[mt][nt][0]), "+f"(acc[mt][nt][1]),
                      "+f"(acc[mt][nt][2]), "+f"(acc[mt][nt][3])
                    : "r"(fa[buf][mt][0]), "r"(fa[buf][mt][1]),
                      "r"(fa[buf][mt][2]), "r"(fa[buf][mt][3]),
                      "r"(fb[buf][nt][0]), "r"(fb[buf][nt][1]));
            }
    };

    load_stage(0, 0);
    load_stage(1, 1);

    for (int ks = 0; ks < NK; ++ks) {
        if (ks + 1 < NK) {
            asm volatile("cp.async.wait_group 1;" ::: "memory");
        } else {
            asm volatile("cp.async.wait_group 0;" ::: "memory");
        }
        __syncthreads();

        const int slot = ks % NSTAGE;
        const uint32_t aOff = smBase + (uint32_t)slot * STAGE_BYTES;
        const uint32_t bOff = aOff + 16384u;

        load_frags(aOff, bOff, 0, 0);
#pragma unroll
        for (int kk = 0; kk < 4; ++kk) {
            if (kk < 3) load_frags(aOff, bOff, kk + 1, (kk + 1) & 1);
            mma_all(kk & 1);
        }
        __syncthreads();

        if (ks + 2 < NK) load_stage(ks + 2, (ks + 2) % NSTAGE);
    }

    // epilogue: bias add, store fp32 (gi/gh) or fp16 (h0)
#pragma unroll
    for (int mt = 0; mt < 4; ++mt) {
        int row = rowBase + warp_m * 64 + mt * 16 + gid;
#pragma unroll
        for (int nt = 0; nt < 8; ++nt) {
            int col = colBase + warp_n * 64 + nt * 8 + tig * 2;
            float b0 = bias[col], b1 = bias[col + 1];
            float2 v0 = make_float2(acc[mt][nt][0] + b0, acc[mt][nt][1] + b1);
            float2 v1 = make_float2(acc[mt][nt][2] + b0, acc[mt][nt][3] + b1);
            if (out_half) {
                __half* C = (__half*)Cv;
                *reinterpret_cast<__half2*>(C + (size_t)row * ldc + col) =
                    __floats2half2_rn(v0.x, v0.y);
                *reinterpret_cast<__half2*>(C + (size_t)(row + 8) * ldc + col) =
                    __floats2half2_rn(v1.x, v1.y);
            } else {
                float* C = (float*)Cv;
                *reinterpret_cast<float2*>(C + (size_t)row * ldc + col) = v0;
                *reinterpret_cast<float2*>(C + (size_t)(row + 8) * ldc + col) = v1;
            }
        }
    }
}

// ---------------------------------------------------------------------------
// Fused gate math + hidden update + output projection.
// 2 rows per 256-thread block; 128 threads per row, 4 hidden units/thread.
// MUFU-only transcendentals; h stored fp16.
// ---------------------------------------------------------------------------
__device__ __forceinline__ float fast_sigmoid(float x) {
    return rcp_fast(1.f + __expf(-x));
}
__device__ __forceinline__ float fast_tanh(float x) {
    float t = __expf(-2.f * fabsf(x));
    float m = (1.f - t) * rcp_fast(1.f + t);
    return copysignf(m, x);
}

__global__ __launch_bounds__(256)
void gate_kernel(const float* __restrict__ W_out,
                 const float* __restrict__ b_out,
                 float* __restrict__ out, int t) {
    int tid = threadIdx.x;
    int row = blockIdx.x * 2 + (tid >> 7);
    int wt = tid & 127;
    float xa = g_x[row * 2 + 0];
    float xb = g_x[row * 2 + 1];

    int j0 = wt * 4;
    const float* gi = &g_gi[(size_t)row * G3];
    const float* gh = &g_gh[(size_t)row * G3];

    float gir[4], giz[4], gin[4], ghr[4], ghz[4], ghn[4], hv[4];
    *reinterpret_cast<float4*>(gir) = *reinterpret_cast<const float4*>(&gi[j0]);
    *reinterpret_cast<float4*>(giz) = *reinterpret_cast<const float4*>(&gi[512 + j0]);
    *reinterpret_cast<float4*>(gin) = *reinterpret_cast<const float4*>(&gi[1024 + j0]);
    *reinterpret_cast<float4*>(ghr) = *reinterpret_cast<const float4*>(&gh[j0]);
    *reinterpret_cast<float4*>(ghz) = *reinterpret_cast<const float4*>(&gh[512 + j0]);
    *reinterpret_cast<float4*>(ghn) = *reinterpret_cast<const float4*>(&gh[1024 + j0]);
    {
        uint2 hraw = *reinterpret_cast<const uint2*>(&g_h[(size_t)row * HID + j0]);
        float2 p0 = __half22float2(*reinterpret_cast<__half2*>(&hraw.x));
        float2 p1 = __half22float2(*reinterpret_cast<__half2*>(&hraw.y));
        hv[0] = p0.x; hv[1] = p0.y; hv[2] = p1.x; hv[3] = p1.y;
    }

    float wr[8], wz[8], wn[8];
    *reinterpret_cast<float4*>(&wr[0]) = *reinterpret_cast<const float4*>(&g_wt[(size_t)j0 * 2]);
    *reinterpret_cast<float4*>(&wr[4]) = *reinterpret_cast<const float4*>(&g_wt[(size_t)j0 * 2 + 4]);
    *reinterpret_cast<float4*>(&wz[0]) = *reinterpret_cast<const float4*>(&g_wt[(size_t)(512 + j0) * 2]);
    *reinterpret_cast<float4*>(&wz[4]) = *reinterpret_cast<const float4*>(&g_wt[(size_t)(512 + j0) * 2 + 4]);
    *reinterpret_cast<float4*>(&wn[0]) = *reinterpret_cast<const float4*>(&g_wt[(size_t)(1024 + j0) * 2]);
    *reinterpret_cast<float4*>(&wn[4]) = *reinterpret_cast<const float4*>(&g_wt[(size_t)(1024 + j0) * 2 + 4]);

    float o0 = 0.f, o1 = 0.f;
    float hn[4];
#pragma unroll
    for (int i = 0; i < 4; ++i) {
        int j = j0 + i;
        float gi_r = gir[i] + xa * wr[i * 2] + xb * wr[i * 2 + 1];
        float gi_z = giz[i] + xa * wz[i * 2] + xb * wz[i * 2 + 1];
        float gi_n = gin[i] + xa * wn[i * 2] + xb * wn[i * 2 + 1];
        float r = fast_sigmoid(gi_r + ghr[i]);
        float u = fast_sigmoid(gi_z + ghz[i]);
        float n = fast_tanh(gi_n + r * ghn[i]);
        float h_new = (1.f - u) * n + u * hv[i];
        hn[i] = h_new;
        o0 += h_new * W_out[j];
        o1 += h_new * W_out[HID + j];
    }
    {
        __half2 p0 = __floats2half2_rn(hn[0], hn[1]);
        __half2 p1 = __floats2half2_rn(hn[2], hn[3]);
        uint2 hraw;
        hraw.x = *reinterpret_cast<uint32_t*>(&p0);
        hraw.y = *reinterpret_cast<uint32_t*>(&p1);
        *reinterpret_cast<uint2*>(&g_h[(size_t)row * HID + j0]) = hraw;
    }

    unsigned m = 0xffffffffu;
#pragma unroll
    for (int off = 16; off; off >>= 1) {
        o0 += __shfl_down_sync(m, o0, off);
        o1 += __shfl_down_sync(m, o1, off);
    }
    __shared__ float s0[8], s1[8];
    int wi = tid >> 5, lane = tid & 31;
    if (lane == 0) { s0[wi] = o0; s1[wi] = o1; }
    __syncthreads();
    if (wt == 0) {
        int base = (tid >> 7) * 4;
        float r0 = s0[base] + s0[base + 1] + s0[base + 2] + s0[base + 3] + b_out[0];
        float r1 = s1[base] + s1[base + 1] + s1[base + 2] + s1[base + 3] + b_out[1];
        out[row * (TSTEPS * 2) + t * 2 + 0] = r0;
        out[row * (TSTEPS * 2) + t * 2 + 1] = r1;
        g_x[row * 2 + 0] = r0;
        g_x[row * 2 + 1] = r1;
    }
}

// ---------------------------------------------------------------------------
// Host launcher
// ---------------------------------------------------------------------------
static void* sym_addr(const void* sym) {
    void* p = nullptr;
    cudaGetSymbolAddress(&p, sym);
    return p;
}

extern "C" void kernel_launch(void* const* d_in, const int* in_sizes, int n_in,
                              void* d_out, int out_size) {
    const float* z     = (const float*)d_in[0];
    const float* x     = (const float*)d_in[1];
    const float* x0    = (const float*)d_in[2];
    const float* W_ia  = (const float*)d_in[3];
    const float* b_ia  = (const float*)d_in[4];
    const float* W_h0  = (const float*)d_in[5];
    const float* b_h0  = (const float*)d_in[6];
    const float* W_ih  = (const float*)d_in[7];
    const float* b_ih  = (const float*)d_in[8];
    const float* W_hh  = (const float*)d_in[9];
    const float* b_hh  = (const float*)d_in[10];
    const float* W_out = (const float*)d_in[11];
    const float* b_out = (const float*)d_in[12];
    float* out = (float*)d_out;

    __half* p_zx  = (__half*)sym_addr(g_zx);
    __half* p_h   = (__half*)sym_addr(g_h);
    float*  p_gi  = (float*)sym_addr(g_gi);
    float*  p_gh  = (float*)sym_addr(g_gh);
    __half* p_wi  = (__half*)sym_addr(g_wi);
    __half* p_wh  = (__half*)sym_addr(g_wh);
    __half* p_wh0 = (__half*)sym_addr(g_wh0);

    cudaFuncSetAttribute(sgemm_mma, cudaFuncAttributeMaxDynamicSharedMemorySize, DSMEM);

    // prologue
    zx_kernel<<<(N_ROWS * 128 + 255) / 256, 256>>>(z, x);
    a0_kernel<<<(N_ROWS + 255) / 256, 256>>>(x0, W_ia, b_ia);
    pack_all<<<(PK_WT + 255) / 256, 256>>>(W_ih, W_hh, W_h0);

    // h0 = zx @ W_h0.T + b_h0   [4096, 512], K=256, fp16 output (MMA operand)
    sgemm_mma<<<dim3(HID / 128, N_ROWS / 128), 128, DSMEM>>>(
        p_zx, KZX, p_wh0, KZX, b_h0, p_h, HID, KZX, 1);
    // gi = zx @ W_ih[:,:256].T + b_ih   [4096, 1536], K=256, fp32 output
    sgemm_mma<<<dim3(G3 / 128, N_ROWS / 128), 128, DSMEM>>>(
        p_zx, KZX, p_wi, KZX, b_ih, p_gi, G3, KZX, 0);

    // recurrent steps
    for (int t = 0; t < TSTEPS; ++t) {
        sgemm_mma<<<dim3(G3 / 128, N_ROWS / 128), 128, DSMEM>>>(
            p_h, HID, p_wh, HID, b_hh, p_gh, G3, HID, 0);
        gate_kernel<<<N_ROWS / 2, 256>>>(W_out, b_out, out, t);
    }
}